// round 2
// baseline (speedup 1.0000x reference)
#include <cuda_runtime.h>

#define B_  16
#define L_  96
#define D_  512
#define M_  (B_ * L_)          // 1536 rows
#define ITILE 8                // i rows per pairwise block
#define NPART (B_ * (L_ / ITILE))   // 192 partial sums

// ---------------- device scratch (no runtime allocation allowed) ------------
__device__ float g_AB[M_ * D_];     // a + b1  (broadcast term of x_i)
__device__ float g_C[M_ * D_];      // c       (broadcast term of x_j)
__device__ float g_u[M_];           // u[i] = sum_h AB[i,h]*w2[h]
__device__ float g_v[M_];           // v[j] = sum_h C[j,h]*w2[h]
__device__ float g_partial[NPART];  // per-block loss partials

// ---------------- kernel 1: fused dual GEMM -------------------------------
// out cols [0,512)  -> g_AB = x @ W1[0:512]  + b1
// out cols [512,1024)-> g_C  = x @ W1[512:1024]
// 64x64 tile, BK=16, 256 threads, 4x4 per-thread register tile.
__global__ void gemm_kernel(const float* __restrict__ X,
                            const float* __restrict__ W1,
                            const float* __restrict__ b1) {
    __shared__ float As[64][16];
    __shared__ float Bs[16][64];

    const int n0 = blockIdx.x * 64;        // 0..960
    const int m0 = blockIdx.y * 64;        // 0..1472
    const bool isA = (n0 < D_);
    const int wRow = isA ? 0 : D_;         // row offset into W1 (2D x D)
    const int wCol = isA ? n0 : (n0 - D_);

    const int tid = threadIdx.x;
    const int tx = tid & 15;
    const int ty = tid >> 4;

    float acc[4][4];
#pragma unroll
    for (int i = 0; i < 4; i++)
#pragma unroll
        for (int j = 0; j < 4; j++) acc[i][j] = 0.f;

    const int ar = tid >> 2, ac = (tid & 3) * 4;   // A-tile load coords
    const int br = tid >> 4, bc = (tid & 15) * 4;  // B-tile load coords

    for (int k0 = 0; k0 < D_; k0 += 16) {
        float4 av = *(const float4*)&X[(size_t)(m0 + ar) * D_ + k0 + ac];
        *(float4*)&As[ar][ac] = av;
        float4 bv = *(const float4*)&W1[(size_t)(wRow + k0 + br) * D_ + wCol + bc];
        *(float4*)&Bs[br][bc] = bv;
        __syncthreads();

#pragma unroll
        for (int kk = 0; kk < 16; kk++) {
            float a0 = As[ty * 4 + 0][kk];
            float a1 = As[ty * 4 + 1][kk];
            float a2 = As[ty * 4 + 2][kk];
            float a3 = As[ty * 4 + 3][kk];
            float4 b4 = *(const float4*)&Bs[kk][tx * 4];
            acc[0][0] = fmaf(a0, b4.x, acc[0][0]);
            acc[0][1] = fmaf(a0, b4.y, acc[0][1]);
            acc[0][2] = fmaf(a0, b4.z, acc[0][2]);
            acc[0][3] = fmaf(a0, b4.w, acc[0][3]);
            acc[1][0] = fmaf(a1, b4.x, acc[1][0]);
            acc[1][1] = fmaf(a1, b4.y, acc[1][1]);
            acc[1][2] = fmaf(a1, b4.z, acc[1][2]);
            acc[1][3] = fmaf(a1, b4.w, acc[1][3]);
            acc[2][0] = fmaf(a2, b4.x, acc[2][0]);
            acc[2][1] = fmaf(a2, b4.y, acc[2][1]);
            acc[2][2] = fmaf(a2, b4.z, acc[2][2]);
            acc[2][3] = fmaf(a2, b4.w, acc[2][3]);
            acc[3][0] = fmaf(a3, b4.x, acc[3][0]);
            acc[3][1] = fmaf(a3, b4.y, acc[3][1]);
            acc[3][2] = fmaf(a3, b4.z, acc[3][2]);
            acc[3][3] = fmaf(a3, b4.w, acc[3][3]);
        }
        __syncthreads();
    }

    if (isA) {
#pragma unroll
        for (int i = 0; i < 4; i++) {
            int row = m0 + ty * 4 + i;
#pragma unroll
            for (int j = 0; j < 4; j++) {
                int col = n0 + tx * 4 + j;
                g_AB[(size_t)row * D_ + col] = acc[i][j] + b1[col];
            }
        }
    } else {
#pragma unroll
        for (int i = 0; i < 4; i++) {
            int row = m0 + ty * 4 + i;
#pragma unroll
            for (int j = 0; j < 4; j++) {
                int col = (n0 - D_) + tx * 4 + j;
                g_C[(size_t)row * D_ + col] = acc[i][j];
            }
        }
    }
}

// ---------------- kernel 2: per-row dot products u, v ----------------------
__global__ void rowdot_kernel(const float* __restrict__ W2) {
    const int gw = (blockIdx.x * blockDim.x + threadIdx.x) >> 5;
    const int lane = threadIdx.x & 31;
    if (gw >= M_) return;
    const float* ab = &g_AB[(size_t)gw * D_];
    const float* cc = &g_C[(size_t)gw * D_];
    float su = 0.f, sv = 0.f;
#pragma unroll 4
    for (int h = lane; h < D_; h += 32) {
        float w = W2[h];
        su = fmaf(ab[h], w, su);
        sv = fmaf(cc[h], w, sv);
    }
#pragma unroll
    for (int o = 16; o > 0; o >>= 1) {
        su += __shfl_xor_sync(0xffffffffu, su, o);
        sv += __shfl_xor_sync(0xffffffffu, sv, o);
    }
    if (lane == 0) { g_u[gw] = su; g_v[gw] = sv; }
}

// ---------------- kernel 3: pairwise |.| reduction + fused softmax-CE ------
// grid = (L/ITILE, B), 256 threads = 8 warps, warp w owns row i = i0 + w.
// lrelu(t) = 0.55 t + 0.45 |t|  (slope 0.1), linear part separated into u+v.
__global__ void pairwise_kernel(const float* __restrict__ W2,
                                const float* __restrict__ b2,
                                const int* __restrict__ order) {
    __shared__ float Cs[16][D_];        // 32 KB j-chunk of C
    __shared__ float rowbuf[ITILE][L_]; // logits rows
    __shared__ int   ord[L_];
    __shared__ float vsh[L_];
    __shared__ float wpart[ITILE];

    const int b  = blockIdx.y;
    const int i0 = blockIdx.x * ITILE;
    const int tid = threadIdx.x;
    const int warp = tid >> 5;
    const int lane = tid & 31;
    const int i = i0 + warp;

    if (tid < L_) {
        ord[tid] = order[b * L_ + tid];
        vsh[tid] = g_v[b * L_ + tid];
    }

    // register-resident ab row (with b1 folded) and w2
    const float* abrow = &g_AB[(size_t)(b * L_ + i) * D_];
    float4 ab4[4], w24[4];
#pragma unroll
    for (int t = 0; t < 4; t++) {
        ab4[t] = *(const float4*)&abrow[t * 128 + lane * 4];
        w24[t] = *(const float4*)&W2[t * 128 + lane * 4];
    }
    const float u   = g_u[b * L_ + i];
    const float b2v = b2[0];

    for (int jc = 0; jc < L_; jc += 16) {
        __syncthreads();
        // cooperative load of 16 C rows (2048 float4 / 256 threads = 8 each)
        for (int t = tid; t < 16 * 128; t += 256) {
            int r = t >> 7, c4 = t & 127;
            ((float4*)&Cs[r][0])[c4] =
                ((const float4*)&g_C[(size_t)(b * L_ + jc + r) * D_])[c4];
        }
        __syncthreads();

        for (int jj = 0; jj < 16; jj++) {
            float acc0 = 0.f, acc1 = 0.f;
#pragma unroll
            for (int t = 0; t < 4; t++) {
                float4 cv = *(const float4*)&Cs[jj][t * 128 + lane * 4];
                float s;
                s = ab4[t].x + cv.x; acc0 = fmaf(fabsf(s), w24[t].x, acc0);
                s = ab4[t].y + cv.y; acc1 = fmaf(fabsf(s), w24[t].y, acc1);
                s = ab4[t].z + cv.z; acc0 = fmaf(fabsf(s), w24[t].z, acc0);
                s = ab4[t].w + cv.w; acc1 = fmaf(fabsf(s), w24[t].w, acc1);
            }
            float acc = acc0 + acc1;
#pragma unroll
            for (int o = 16; o > 0; o >>= 1)
                acc += __shfl_xor_sync(0xffffffffu, acc, o);
            if (lane == 0) {
                int j = jc + jj;
                rowbuf[warp][j] = 0.55f * (u + vsh[j]) + 0.45f * acc + b2v;
            }
        }
    }
    __syncthreads();

    // ---- fused cross-entropy for row i (TAU = 1) ----
    float l0 = rowbuf[warp][lane];
    float l1 = rowbuf[warp][lane + 32];
    float l2 = rowbuf[warp][lane + 64];
    float m = fmaxf(l0, fmaxf(l1, l2));
#pragma unroll
    for (int o = 16; o > 0; o >>= 1)
        m = fmaxf(m, __shfl_xor_sync(0xffffffffu, m, o));
    float s = expf(l0 - m) + expf(l1 - m) + expf(l2 - m);
#pragma unroll
    for (int o = 16; o > 0; o >>= 1)
        s += __shfl_xor_sync(0xffffffffu, s, o);
    float lse = m + logf(s);

    // target: FIRST j with order[j] == order[i]+1, else 0 (argmax semantics)
    int oi = ord[i];
    int o0 = ord[lane], o1 = ord[lane + 32], o2 = ord[lane + 64];
    unsigned t0 = __ballot_sync(0xffffffffu, o0 == oi + 1);
    unsigned t1 = __ballot_sync(0xffffffffu, o1 == oi + 1);
    unsigned t2 = __ballot_sync(0xffffffffu, o2 == oi + 1);
    int tgt = t0 ? (__ffs(t0) - 1)
                 : (t1 ? (31 + __ffs(t1)) : (t2 ? (63 + __ffs(t2)) : 0));

    // last = FIRST argmax of order row (ignore_index position)
    int mx = max(o0, max(o1, o2));
#pragma unroll
    for (int o = 16; o > 0; o >>= 1)
        mx = max(mx, __shfl_xor_sync(0xffffffffu, mx, o));
    unsigned M0 = __ballot_sync(0xffffffffu, o0 == mx);
    unsigned M1 = __ballot_sync(0xffffffffu, o1 == mx);
    unsigned M2 = __ballot_sync(0xffffffffu, o2 == mx);
    int last = M0 ? (__ffs(M0) - 1) : (M1 ? (31 + __ffs(M1)) : (63 + __ffs(M2)));

    float contrib = (i == last) ? 0.f : (lse - rowbuf[warp][tgt]);
    if (lane == 0) wpart[warp] = contrib;
    __syncthreads();
    if (tid == 0) {
        float ssum = 0.f;
#pragma unroll
        for (int w = 0; w < ITILE; w++) ssum += wpart[w];
        g_partial[b * (L_ / ITILE) + blockIdx.x] = ssum;
    }
}

// ---------------- kernel 4: deterministic final reduction ------------------
__global__ void finalize_kernel(float* __restrict__ out) {
    __shared__ float sh[NPART];
    int t = threadIdx.x;
    if (t < NPART) sh[t] = g_partial[t];
    __syncthreads();
    if (t == 0) {
        float s = 0.f;
        for (int k = 0; k < NPART; k++) s += sh[k];
        // loss = (1/B) * sum_b [ sum_i -logp / 95 ]   (valid = L-1 = 95 rows/sample)
        out[0] = s * (1.0f / (16.0f * 95.0f));
    }
}

// ---------------- launcher --------------------------------------------------
extern "C" void kernel_launch(void* const* d_in, const int* in_sizes, int n_in,
                              void* d_out, int out_size) {
    const float* X    = (const float*)d_in[0];   // inputs [16,96,512]
    const float* W1   = (const float*)d_in[1];   // [1024,512]
    const float* b1   = (const float*)d_in[2];   // [512]
    const float* W2   = (const float*)d_in[3];   // [512,1]
    const float* b2   = (const float*)d_in[4];   // [1]
    // d_in[5] = mask (all ones, unused)
    const int*   order = (const int*)d_in[6];    // [16,96]

    gemm_kernel<<<dim3(16, 24), 256>>>(X, W1, b1);
    rowdot_kernel<<<192, 256>>>(W2);
    pairwise_kernel<<<dim3(L_ / ITILE, B_), 256>>>(W2, b2, order);
    finalize_kernel<<<1, 256>>>((float*)d_out);
}